// round 2
// baseline (speedup 1.0000x reference)
#include <cuda_runtime.h>

// CRF NLL, exp-domain forward scan with packed f32x2 FMAs.
// B=512, S=512, T=64. One block (64 threads = 2 warps) per batch.
// q_s[to] = (sum_from q_{s-1}[from] * E[from,to]) * exp(f_s[to]) / q_{s-1}[0]
// C_s = C_{s-1} + log(q_{s-1}[0]);  part_s = log(q_s) + C_s.

constexpr int Bb = 512;
constexpr int Ss = 512;
constexpr int Tt = 64;
constexpr int START = Tt - 2;
constexpr int STOP  = Tt - 1;

__device__ float g_partial[Bb];
__device__ unsigned int g_count = 0;

typedef unsigned long long u64;

static __device__ __forceinline__ u64 fma2(u64 a, u64 b, u64 c) {
    u64 d;
    asm("fma.rn.f32x2 %0, %1, %2, %3;" : "=l"(d) : "l"(a), "l"(b), "l"(c));
    return d;
}
static __device__ __forceinline__ u64 add2(u64 a, u64 b) {
    u64 d;
    asm("add.rn.f32x2 %0, %1, %2;" : "=l"(d) : "l"(a), "l"(b));
    return d;
}
static __device__ __forceinline__ u64 pack2(float lo, float hi) {
    u64 d;
    asm("mov.b64 %0, {%1, %2};" : "=l"(d) : "f"(lo), "f"(hi));
    return d;
}
static __device__ __forceinline__ void unpack2(u64 v, float& lo, float& hi) {
    asm("mov.b64 {%0, %1}, %2;" : "=f"(lo), "=f"(hi) : "l"(v));
}
static __device__ __forceinline__ float rcp_approx(float x) {
    float r;
    asm("rcp.approx.f32 %0, %1;" : "=f"(r) : "f"(x));
    return r;
}

__global__ __launch_bounds__(Tt) void crf_kernel(
    const float* __restrict__ feats,
    const unsigned char* __restrict__ mask8,
    const int* __restrict__ tags,
    const float* __restrict__ trans,
    float* __restrict__ out)
{
    const int b  = blockIdx.x;
    const int to = threadIdx.x;   // 0..63

    __shared__ ulonglong2 qbuf[2][16];   // 64 floats per buffer (q in exp domain)
    __shared__ float red[Tt];
    __shared__ int   ired[Tt];
    __shared__ int   shL;
    __shared__ bool  is_last;

    // ---- mask layout probe (uint8 vs int32) + sequence length ----
    const int* mask32 = reinterpret_cast<const int*>(mask8);
    const bool is32 = (mask8[0] == 1 && mask8[1] == 0 && mask8[2] == 0 && mask8[3] == 0);

    int cnt = 0;
    #pragma unroll
    for (int k = 0; k < Ss / Tt; ++k) {
        int s  = to + k * Tt;
        int mv = is32 ? mask32[b * Ss + s] : (int)mask8[b * Ss + s];
        cnt += (mv != 0);
    }
    ired[to] = cnt;
    __syncthreads();
    if (to == 0) {
        int L = 0;
        #pragma unroll
        for (int i = 0; i < Tt; ++i) L += ired[i];
        shL = L;
    }
    __syncthreads();
    const int L = shL;   // guaranteed >= S/2 = 256

    const float* fb = feats + (size_t)b * Ss * Tt;
    const int*   tg = tags + b * Ss;

    // ---- gold path score ----
    float gsum = 0.f;
    for (int s = to; s < L; s += Tt) {
        int t1 = tg[s];
        int t0 = (s == 0) ? START : tg[s - 1];
        gsum += fb[s * Tt + t1] + trans[t0 * Tt + t1];
    }
    red[to] = gsum;
    __syncthreads();
    float gold = 0.f;
    if (to == 0) {
        #pragma unroll
        for (int i = 0; i < Tt; ++i) gold += red[i];
        gold += trans[tg[L - 1] * Tt + STOP];
    }
    __syncthreads();

    // ---- E pairs: E2[k] = (exp(trans[2k][to]), exp(trans[2k+1][to])) ----
    u64 E2[Tt / 2];
    #pragma unroll
    for (int k = 0; k < Tt / 2; ++k) {
        float lo = __expf(trans[(2 * k)     * Tt + to]);
        float hi = __expf(trans[(2 * k + 1) * Tt + to]);
        E2[k] = pack2(lo, hi);
    }

    // ---- init: part_0 = f_0 + trans[START,:]; q_0 = exp(part_0 - part_0[0]) ----
    const float part0 = fb[to] + trans[START * Tt + to];
    const float c0    = fb[0]  + trans[START * Tt];      // broadcast loads
    float logC = c0;
    reinterpret_cast<float*>(qbuf[0])[to] = __expf(part0 - c0);
    __syncthreads();

    float ef  = __expf(fb[Tt + to]);   // exp(feats) for s=1 (L >= 256)
    float cur = 0.f;

    // ---- forward scan ----
    for (int s = 1; s < L; ++s) {
        const ulonglong2* qp = qbuf[(s - 1) & 1];

        ulonglong2 w = qp[0];
        float q0, q1dummy;
        unpack2(w.x, q0, q1dummy);
        const float sc = ef * rcp_approx(q0);   // off critical path (overlaps FMA loop)
        logC += __logf(q0);                     // independent side chain

        u64 acc[4];
        acc[0] = fma2(w.x, E2[0], 0ull);
        acc[1] = fma2(w.y, E2[1], 0ull);
        acc[2] = 0ull;
        acc[3] = 0ull;
        #pragma unroll
        for (int j = 1; j < 16; ++j) {
            w = qp[j];
            acc[(2 * j)     & 3] = fma2(w.x, E2[2 * j],     acc[(2 * j)     & 3]);
            acc[(2 * j + 1) & 3] = fma2(w.y, E2[2 * j + 1], acc[(2 * j + 1) & 3]);
        }
        const u64 t = add2(add2(acc[0], acc[2]), add2(acc[1], acc[3]));
        float lo, hi;
        unpack2(t, lo, hi);
        const float raw = (lo + hi) * sc;

        if (s + 1 < L) ef = __expf(fb[(s + 1) * Tt + to]);  // prefetch next exp(f)

        reinterpret_cast<float*>(qbuf[s & 1])[to] = raw;
        cur = raw;
        __syncthreads();
    }

    // ---- final transition to STOP ----
    red[to] = cur * __expf(trans[to * Tt + STOP]);
    __syncthreads();
    if (to == 0) {
        float tot = 0.f;
        #pragma unroll
        for (int i = 0; i < Tt; ++i) tot += red[i];
        const float fwd = logC + __logf(tot);
        g_partial[b] = fwd - gold;
        __threadfence();
        unsigned int c = atomicAdd(&g_count, 1u);
        is_last = (c == (unsigned)gridDim.x - 1);
    }
    __syncthreads();

    // ---- last block: deterministic fixed-order reduction over batches ----
    if (is_last) {
        __threadfence();
        float sum = 0.f;
        #pragma unroll
        for (int k = 0; k < Bb / Tt; ++k) {
            float v;
            asm volatile("ld.global.cg.f32 %0, [%1];" : "=f"(v)
                         : "l"(&g_partial[to + k * Tt]));
            sum += v;
        }
        red[to] = sum;
        __syncthreads();
        if (to == 0) {
            float tot = 0.f;
            #pragma unroll
            for (int i = 0; i < Tt; ++i) tot += red[i];
            out[0] = tot;
            g_count = 0;   // reset for next (graph-replayed) launch
        }
    }
}

extern "C" void kernel_launch(void* const* d_in, const int* in_sizes, int n_in,
                              void* d_out, int out_size)
{
    (void)in_sizes; (void)n_in; (void)out_size;
    const float*         feats = (const float*)d_in[0];
    const unsigned char* mask  = (const unsigned char*)d_in[1];
    const int*           tags  = (const int*)d_in[2];
    const float*         trans = (const float*)d_in[3];

    crf_kernel<<<Bb, Tt>>>(feats, mask, tags, trans, (float*)d_out);
}

// round 3
// speedup vs baseline: 1.6842x; 1.6842x over previous
#include <cuda_runtime.h>

// CRF NLL, exp-domain forward scan, packed f32x2 FMAs, 8-deep feats prefetch.
// B=512, S=512, T=64. One block (64 threads = 2 warps) per batch.
// q_s[to] = (sum_from q_{s-1}[from] * E[from,to]) * exp(f_s[to]) / q_{s-1}[0]
// C_s = C_{s-1} + log(q_{s-1}[0]);  part_s = log(q_s) + C_s.

constexpr int Bb = 512;
constexpr int Ss = 512;
constexpr int Tt = 64;
constexpr int START = Tt - 2;
constexpr int STOP  = Tt - 1;
constexpr int PD    = 8;     // prefetch depth (steps)

__device__ float g_partial[Bb];
__device__ unsigned int g_count = 0;

typedef unsigned long long u64;

static __device__ __forceinline__ u64 fma2(u64 a, u64 b, u64 c) {
    u64 d;
    asm("fma.rn.f32x2 %0, %1, %2, %3;" : "=l"(d) : "l"(a), "l"(b), "l"(c));
    return d;
}
static __device__ __forceinline__ u64 add2(u64 a, u64 b) {
    u64 d;
    asm("add.rn.f32x2 %0, %1, %2;" : "=l"(d) : "l"(a), "l"(b));
    return d;
}
static __device__ __forceinline__ u64 pack2(float lo, float hi) {
    u64 d;
    asm("mov.b64 %0, {%1, %2};" : "=l"(d) : "f"(lo), "f"(hi));
    return d;
}
static __device__ __forceinline__ void unpack2(u64 v, float& lo, float& hi) {
    asm("mov.b64 {%0, %1}, %2;" : "=f"(lo), "=f"(hi) : "l"(v));
}
static __device__ __forceinline__ float rcp_approx(float x) {
    float r;
    asm("rcp.approx.f32 %0, %1;" : "=f"(r) : "f"(x));
    return r;
}

__global__ __launch_bounds__(Tt) void crf_kernel(
    const float* __restrict__ feats,
    const unsigned char* __restrict__ mask8,
    const int* __restrict__ tags,
    const float* __restrict__ trans,
    float* __restrict__ out)
{
    const int b  = blockIdx.x;
    const int to = threadIdx.x;   // 0..63

    __shared__ ulonglong2 qbuf[2][16];   // 64 floats per buffer (q in exp domain)
    __shared__ float red[Tt];
    __shared__ int   ired[Tt];
    __shared__ int   shL;
    __shared__ bool  is_last;

    // ---- mask layout probe (uint8 vs int32) + sequence length ----
    const int* mask32 = reinterpret_cast<const int*>(mask8);
    const bool is32 = (mask8[0] == 1 && mask8[1] == 0 && mask8[2] == 0 && mask8[3] == 0);

    int cnt = 0;
    #pragma unroll
    for (int k = 0; k < Ss / Tt; ++k) {
        int s  = to + k * Tt;
        int mv = is32 ? mask32[b * Ss + s] : (int)mask8[b * Ss + s];
        cnt += (mv != 0);
    }
    ired[to] = cnt;
    __syncthreads();
    if (to == 0) {
        int L = 0;
        #pragma unroll
        for (int i = 0; i < Tt; ++i) L += ired[i];
        shL = L;
    }
    __syncthreads();
    const int L = shL;   // guaranteed >= S/2 = 256

    const float* fb = feats + (size_t)b * Ss * Tt;
    const int*   tg = tags + b * Ss;

    // ---- gold path score ----
    float gsum = 0.f;
    for (int s = to; s < L; s += Tt) {
        int t1 = tg[s];
        int t0 = (s == 0) ? START : tg[s - 1];
        gsum += fb[s * Tt + t1] + trans[t0 * Tt + t1];
    }
    red[to] = gsum;
    __syncthreads();
    float gold = 0.f;
    if (to == 0) {
        #pragma unroll
        for (int i = 0; i < Tt; ++i) gold += red[i];
        gold += trans[tg[L - 1] * Tt + STOP];
    }
    __syncthreads();

    // ---- E pairs: E2[k] = (exp(trans[2k][to]), exp(trans[2k+1][to])) ----
    u64 E2[Tt / 2];
    #pragma unroll
    for (int k = 0; k < Tt / 2; ++k) {
        float lo = __expf(trans[(2 * k)     * Tt + to]);
        float hi = __expf(trans[(2 * k + 1) * Tt + to]);
        E2[k] = pack2(lo, hi);
    }

    // ---- init: part_0 = f_0 + trans[START,:]; q_0 = exp(part_0 - part_0[0]) ----
    const float part0 = fb[to] + trans[START * Tt + to];
    const float c0    = fb[0]  + trans[START * Tt];      // broadcast loads
    float logC = c0;
    reinterpret_cast<float*>(qbuf[0])[to] = __expf(part0 - c0);
    __syncthreads();

    // ---- feats pipeline: fp[r] holds raw f for step s where (s-1)&7 == r ----
    float fp[PD];
    #pragma unroll
    for (int r = 0; r < PD; ++r) fp[r] = fb[(1 + r) * Tt + to];   // steps 1..8 (L >= 256)

    float cur = 0.f;

    // ---- one scan step (consumes raw feature f for step s) ----
    auto step = [&](int s, float f) {
        const ulonglong2* qp = qbuf[(s - 1) & 1];

        ulonglong2 w = qp[0];
        float q0, q1d;
        unpack2(w.x, q0, q1d);
        const float sc = __expf(f) * rcp_approx(q0);  // overlaps FMA loop
        logC += __logf(q0);                           // independent side chain

        u64 acc0 = fma2(w.x, E2[0], 0ull);
        u64 acc1 = fma2(w.y, E2[1], 0ull);
        u64 acc2 = 0ull, acc3 = 0ull;
        #pragma unroll
        for (int j = 1; j < 16; ++j) {
            w = qp[j];
            if (j & 1) { acc2 = fma2(w.x, E2[2 * j], acc2); acc3 = fma2(w.y, E2[2 * j + 1], acc3); }
            else       { acc0 = fma2(w.x, E2[2 * j], acc0); acc1 = fma2(w.y, E2[2 * j + 1], acc1); }
        }
        const u64 t = add2(add2(acc0, acc2), add2(acc1, acc3));
        float lo, hi;
        unpack2(t, lo, hi);
        const float raw = (lo + hi) * sc;

        reinterpret_cast<float*>(qbuf[s & 1])[to] = raw;
        cur = raw;
        __syncthreads();
    };

    // ---- forward scan, unrolled x8 with deep prefetch ----
    int s = 1;
    for (; s + (PD - 1) < L; ) {
        #pragma unroll
        for (int r = 0; r < PD; ++r) {
            const float f = fp[r];
            if (s + PD < L) fp[r] = fb[(s + PD) * Tt + to];   // prefetch step s+8
            step(s, f);
            ++s;
        }
    }
    for (; s < L; ++s) {
        step(s, fp[(s - 1) & (PD - 1)]);
    }

    // ---- final transition to STOP ----
    red[to] = cur * __expf(trans[to * Tt + STOP]);
    __syncthreads();
    if (to == 0) {
        float tot = 0.f;
        #pragma unroll
        for (int i = 0; i < Tt; ++i) tot += red[i];
        const float fwd = logC + __logf(tot);
        g_partial[b] = fwd - gold;
        __threadfence();
        unsigned int c = atomicAdd(&g_count, 1u);
        is_last = (c == (unsigned)gridDim.x - 1);
    }
    __syncthreads();

    // ---- last block: deterministic fixed-order reduction over batches ----
    if (is_last) {
        __threadfence();
        float sum = 0.f;
        #pragma unroll
        for (int k = 0; k < Bb / Tt; ++k) {
            float v;
            asm volatile("ld.global.cg.f32 %0, [%1];" : "=f"(v)
                         : "l"(&g_partial[to + k * Tt]));
            sum += v;
        }
        red[to] = sum;
        __syncthreads();
        if (to == 0) {
            float tot = 0.f;
            #pragma unroll
            for (int i = 0; i < Tt; ++i) tot += red[i];
            out[0] = tot;
            g_count = 0;   // reset for next (graph-replayed) launch
        }
    }
}

extern "C" void kernel_launch(void* const* d_in, const int* in_sizes, int n_in,
                              void* d_out, int out_size)
{
    (void)in_sizes; (void)n_in; (void)out_size;
    const float*         feats = (const float*)d_in[0];
    const unsigned char* mask  = (const unsigned char*)d_in[1];
    const int*           tags  = (const int*)d_in[2];
    const float*         trans = (const float*)d_in[3];

    crf_kernel<<<Bb, Tt>>>(feats, mask, tags, trans, (float*)d_out);
}